// round 15
// baseline (speedup 1.0000x reference)
#include <cuda_runtime.h>
#include <cuda_fp16.h>
#include <cstdint>

#define DD 256
#define BB 16
#define NN 2048
#define ROWS (BB*NN)

typedef __half h16;

// ------------------------------------------------------------------ scratch
__device__ float g_W[DD*DD];                 // Wq @ Wk^T
__device__ float g_u[DD];                    // Wk @ bq
__device__ float g_c[ROWS];                  // X . u  (per key row)
__device__ float g_cpart[(size_t)ROWS*4];    // c partials per d-tile
__device__ float g_mt[(size_t)ROWS*16];      // per (row, ntile) max
__device__ float g_st[(size_t)ROWS*16];      // per (row, ntile) sum
__device__ float g_cf[(size_t)ROWS*16];      // per (row, ntile) exp(mt-m)/l

__device__ h16 g_Xh[(size_t)ROWS*DD],  g_Xl[(size_t)ROWS*DD];    // X splits (row-major)
__device__ h16 g_Xth[(size_t)BB*DD*NN];                          // X^T (hi only)
__device__ h16 g_Aph[(size_t)ROWS*DD];                           // A' = X@W (fp16)
__device__ h16 g_Pt[(size_t)ROWS*NN];                            // exp(s - m_tile) fp16
__device__ h16 g_aggh[(size_t)ROWS*DD], g_aggl[(size_t)ROWS*DD]; // agg splits
__device__ h16 g_Wth[DD*DD], g_Wtl[DD*DD];   // (WqWk^T)^T splits
__device__ h16 g_Woth[DD*DD], g_Wotl[DD*DD]; // Wo^T splits

// ------------------------------------------------------------------ helpers
__device__ __forceinline__ uint32_t smem_u32(const void* p) {
    uint32_t a;
    asm("{ .reg .u64 t; cvta.to.shared.u64 t, %1; cvt.u32.u64 %0, t; }" : "=r"(a) : "l"(p));
    return a;
}
#define CP16(dst, src) \
    asm volatile("cp.async.cg.shared.global [%0], [%1], 16;" :: "r"(dst), "l"(src))
#define CP_COMMIT() asm volatile("cp.async.commit_group;" ::: "memory")
#define CP_WAIT(n)  asm volatile("cp.async.wait_group %0;" :: "n"(n) : "memory")

#define MMA16816(c, a, b)                                                     \
    asm volatile("mma.sync.aligned.m16n8k16.row.col.f32.f16.f16.f32 "         \
        "{%0,%1,%2,%3},{%4,%5,%6,%7},{%8,%9},{%0,%1,%2,%3};"                  \
        : "+f"((c)[0]), "+f"((c)[1]), "+f"((c)[2]), "+f"((c)[3])              \
        : "r"((a)[0]), "r"((a)[1]), "r"((a)[2]), "r"((a)[3]),                 \
          "r"((b)[0]), "r"((b)[1]))

#define LDSM4(r0, r1, r2, r3, addr)                                           \
    asm volatile("ldmatrix.sync.aligned.m8n8.x4.shared.b16 {%0,%1,%2,%3}, [%4];" \
        : "=r"(r0), "=r"(r1), "=r"(r2), "=r"(r3) : "r"(addr))

__device__ __forceinline__ void split2(float f, h16& h, h16& l) {
    h = __float2half_rn(f);
    l = __float2half_rn(f - __half2float(h));
}
__device__ __forceinline__ uint32_t packh2(h16 a, h16 b) {
    __half2 p = __halves2half2(a, b);
    return *reinterpret_cast<uint32_t*>(&p);
}

// ------------------------------------------------------------------ precompute: W = Wq@Wk^T, u = Wk@bq
__global__ void k_precomp(const float* __restrict__ Wq, const float* __restrict__ Wk,
                          const float* __restrict__ bq) {
    __shared__ float v[DD];
    int bx = blockIdx.x;
    if (bx < DD) {
        v[threadIdx.x] = Wq[bx*DD + threadIdx.x];
        __syncthreads();
        int j = threadIdx.x;
        const float* wk = Wk + j*DD;
        float s = 0.f;
#pragma unroll 8
        for (int e = 0; e < DD; e++) s += v[e] * wk[e];
        g_W[bx*DD + j] = s;
    } else {
        v[threadIdx.x] = bq[threadIdx.x];
        __syncthreads();
        int i = threadIdx.x;
        const float* wk = Wk + i*DD;
        float s = 0.f;
#pragma unroll 8
        for (int e = 0; e < DD; e++) s += wk[e] * v[e];
        g_u[i] = s;
    }
}

// ------------------------------------------------------------------ tile-based prep (one X pass)
// blocks [0,512): W/Wo transpose+split
// blocks [512,2560): 64x64 X tile -> Xh/Xl (vectorized), Xth (hi), c partials
__global__ __launch_bounds__(256) void k_prep(const float* __restrict__ X,
                                              const float* __restrict__ Wo) {
    __shared__ float t[64][65];
    __shared__ float us[64];
    int bx = blockIdx.x, tid = threadIdx.x;
    if (bx < 512) {
        int which = bx >> 8, j = bx & 255, d = tid;
        const float* src = which ? Wo : g_W;
        h16* dh = which ? g_Woth : g_Wth;
        h16* dl = which ? g_Wotl : g_Wtl;
        float f = src[d*DD + j];
        split2(f, dh[j*DD + d], dl[j*DD + d]);
        return;
    }
    int idx = bx - 512;                 // 32 x 4 x 16
    int n0 = (idx & 31) * 64, d0 = ((idx >> 5) & 3) * 64, b = idx >> 7;
    const float* Xb = X + (size_t)b * NN * DD;

    if (tid < 64) us[tid] = g_u[d0 + tid];
    // load 64x64 fp32 tile (rows = n, cols = d)
    for (int u = tid; u < 64*16; u += 256) {
        int r = u >> 4, c4 = u & 15;
        float4 v = *(const float4*)(Xb + (size_t)(n0 + r)*DD + d0 + c4*4);
        t[r][c4*4+0] = v.x; t[r][c4*4+1] = v.y; t[r][c4*4+2] = v.z; t[r][c4*4+3] = v.w;
    }
    __syncthreads();

    // c partials: 4 threads per row, 16 cols each, shfl-reduce
    {
        int r = tid >> 2, part = tid & 3;
        float s = 0.f;
#pragma unroll
        for (int k = 0; k < 16; k++) s += t[r][part*16 + k] * us[part*16 + k];
        s += __shfl_xor_sync(0xffffffffu, s, 1);
        s += __shfl_xor_sync(0xffffffffu, s, 2);
        if (part == 0)
            g_cpart[(size_t)(b*NN + n0 + r)*4 + (d0 >> 6)] = s;
    }

    // Xh/Xl: row-major, 4 cols per task -> uint2 stores
    for (int u = tid; u < 1024; u += 256) {
        int r = u >> 4, cq = u & 15;
        float v0 = t[r][cq*4+0], v1 = t[r][cq*4+1];
        float v2 = t[r][cq*4+2], v3 = t[r][cq*4+3];
        h16 h0,l0,h1,l1,h2,l2,h3,l3;
        split2(v0,h0,l0); split2(v1,h1,l1); split2(v2,h2,l2); split2(v3,h3,l3);
        size_t o = (size_t)(b*NN + n0 + r)*DD + d0 + cq*4;
        *(uint2*)(g_Xh + o) = make_uint2(packh2(h0,h1), packh2(h2,h3));
        *(uint2*)(g_Xl + o) = make_uint2(packh2(l0,l1), packh2(l2,l3));
    }

    // Xth (hi only): row d gets contiguous n -> uint2 stores
    size_t ob = (size_t)b * DD * NN;
    for (int u = tid; u < 1024; u += 256) {
        int d = u >> 4, nq = u & 15;
        h16 h0 = __float2half_rn(t[nq*4+0][d]);
        h16 h1 = __float2half_rn(t[nq*4+1][d]);
        h16 h2 = __float2half_rn(t[nq*4+2][d]);
        h16 h3 = __float2half_rn(t[nq*4+3][d]);
        *(uint2*)(g_Xth + ob + (size_t)(d0 + d)*NN + n0 + nq*4) =
            make_uint2(packh2(h0,h1), packh2(h2,h3));
    }
}

// reduce c partials (fixed order -> deterministic)
__global__ __launch_bounds__(256) void k_csum() {
    int r = blockIdx.x * 256 + threadIdx.x;
    float4 p = *(const float4*)(g_cpart + (size_t)r*4);
    g_c[r] = ((p.x + p.y) + p.z) + p.w;
}

// per-row normalization: m = max mt, l = sum st*exp(mt-m), cf = exp(mt-m)/l
__global__ __launch_bounds__(256) void k_norm() {
    int r = blockIdx.x * 256 + threadIdx.x;
    float mt[16], m = -1e30f;
#pragma unroll
    for (int q = 0; q < 16; q++) {
        mt[q] = g_mt[(size_t)r*16 + q];
        m = fmaxf(m, mt[q]);
    }
    float e[16], l = 0.f;
#pragma unroll
    for (int q = 0; q < 16; q++) {
        e[q] = __expf(mt[q] - m);
        l += g_st[(size_t)r*16 + q] * e[q];
    }
    float inv = 1.f / l;
#pragma unroll
    for (int q = 0; q < 16; q++)
        g_cf[(size_t)r*16 + q] = e[q] * inv;
}

// ------------------------------------------------------------------ HMMA GEMM (32-K chunks, small 3-combo GEMMs)
#define TPAD   40
#define TILE_B (128*TPAD*2)       // 10240
#define OFF_AH 0
#define OFF_AL (1*TILE_B)
#define OFF_BH (2*TILE_B)
#define OFF_BL (3*TILE_B)
#define STAGE_B (4*TILE_B)        // 40960
#define GEMM_SMEM (2*STAGE_B)     // 81920

// EPI: 2 = bias+relu fp32   3 = fp16 hi-only
template<int EPI, int COMBOS>
__global__ __launch_bounds__(256, 2) void k_gemm(
    const h16* __restrict__ Ah, const h16* __restrict__ Al,
    const h16* __restrict__ Bh, const h16* __restrict__ Bl,
    float* __restrict__ Cf, h16* __restrict__ Ch,
    const float* __restrict__ bias,
    int K, int ldc, size_t sC)
{
    extern __shared__ char smem[];
    uint32_t sb = smem_u32(smem);
    int tid = threadIdx.x;
    int lane = tid & 31, wid = tid >> 5;
    int g = lane >> 2, t = lane & 3;
    int warp_m = (wid & 1) * 64;
    int warp_n = (wid >> 1) * 32;
    int m0 = blockIdx.x * 128, n0 = blockIdx.y * 128, b = blockIdx.z;

    size_t go0 = (size_t)(tid >> 2) * K + (tid & 3) * 8;
    size_t go1 = go0 + (size_t)64 * K;
    uint32_t do0 = (uint32_t)((tid >> 2) * 80 + (tid & 3) * 16);
    uint32_t do1 = do0 + 64*80;

    int lr = ((lane >> 3) & 1) * 8 + (lane & 7);
    int lk = (lane >> 4) * 16;
    uint32_t a_off[4], b_off[2];
#pragma unroll
    for (int i = 0; i < 4; i++) a_off[i] = (uint32_t)((warp_m + i*16 + lr)*80 + lk);
#pragma unroll
    for (int p = 0; p < 2; p++) b_off[p] = (uint32_t)((warp_n + p*16 + lr)*80 + lk);

    const h16* pAh = Ah + (size_t)m0*K;
    const h16* pAl = (COMBOS >= 3) ? Al + (size_t)m0*K : nullptr;
    const h16* pBh = Bh + (size_t)n0*K;
    const h16* pBl = (COMBOS >= 2) ? Bl + (size_t)n0*K : nullptr;

    float acc[4][4][4];
#pragma unroll
    for (int i = 0; i < 4; i++)
#pragma unroll
        for (int j = 0; j < 4; j++)
#pragma unroll
            for (int r = 0; r < 4; r++) acc[i][j][r] = 0.f;

#define ISSUE_CHUNK(sbase, k0) do {                                          \
        CP16((sbase) + OFF_AH + do0, pAh + go0 + (k0));                      \
        CP16((sbase) + OFF_AH + do1, pAh + go1 + (k0));                      \
        if (COMBOS >= 3) {                                                   \
            CP16((sbase) + OFF_AL + do0, pAl + go0 + (k0));                  \
            CP16((sbase) + OFF_AL + do1, pAl + go1 + (k0));                  \
        }                                                                    \
        CP16((sbase) + OFF_BH + do0, pBh + go0 + (k0));                      \
        CP16((sbase) + OFF_BH + do1, pBh + go1 + (k0));                      \
        if (COMBOS >= 2) {                                                   \
            CP16((sbase) + OFF_BL + do0, pBl + go0 + (k0));                  \
            CP16((sbase) + OFF_BL + do1, pBl + go1 + (k0));                  \
        }                                                                    \
    } while (0)

    int nchunk = K >> 5;
    ISSUE_CHUNK(sb, 0);
    CP_COMMIT();

    for (int ch = 0; ch < nchunk; ch++) {
        int st = ch & 1;
        if (ch + 1 < nchunk) {
            ISSUE_CHUNK(sb + (uint32_t)(st ^ 1)*STAGE_B, (ch+1) << 5);
            CP_COMMIT();
            CP_WAIT(1);
        } else {
            CP_WAIT(0);
        }
        __syncthreads();

        uint32_t base = sb + (uint32_t)st * STAGE_B;
#pragma unroll
        for (int ks = 0; ks < 2; ks++) {
            uint32_t kb = ks * 32;
            uint32_t ah[4][4], al[4][4], bh[4][2], bl[4][2];
#pragma unroll
            for (int i = 0; i < 4; i++) {
                LDSM4(ah[i][0], ah[i][1], ah[i][2], ah[i][3], base + OFF_AH + a_off[i] + kb);
                if (COMBOS >= 3)
                    LDSM4(al[i][0], al[i][1], al[i][2], al[i][3], base + OFF_AL + a_off[i] + kb);
            }
#pragma unroll
            for (int p = 0; p < 2; p++) {
                LDSM4(bh[2*p][0], bh[2*p+1][0], bh[2*p][1], bh[2*p+1][1],
                      base + OFF_BH + b_off[p] + kb);
                if (COMBOS >= 2)
                    LDSM4(bl[2*p][0], bl[2*p+1][0], bl[2*p][1], bl[2*p+1][1],
                          base + OFF_BL + b_off[p] + kb);
            }
#pragma unroll
            for (int i = 0; i < 4; i++)
#pragma unroll
                for (int j = 0; j < 4; j++) {
                    MMA16816(acc[i][j], ah[i], bh[j]);
                    if (COMBOS >= 2) MMA16816(acc[i][j], ah[i], bl[j]);
                    if (COMBOS >= 3) MMA16816(acc[i][j], al[i], bh[j]);
                }
        }
        __syncthreads();
    }

#pragma unroll
    for (int i = 0; i < 4; i++) {
        int row0 = m0 + warp_m + i*16 + g;
#pragma unroll
        for (int j = 0; j < 4; j++) {
            int col = n0 + warp_n + j*8 + 2*t;
            if (EPI == 3) {
                size_t o0 = (size_t)row0*ldc + col;
                size_t o1 = o0 + 8*(size_t)ldc;
                *(__half2*)(Ch + o0) = __floats2half2_rn(acc[i][j][0], acc[i][j][1]);
                *(__half2*)(Ch + o1) = __floats2half2_rn(acc[i][j][2], acc[i][j][3]);
            } else {
                float b0 = bias[col], b1 = bias[col+1];
                float* d0 = Cf + (size_t)row0*ldc + col;
                float* d1 = d0 + 8*ldc;
                *(float2*)d0 = make_float2(fmaxf(acc[i][j][0]+b0, 0.f),
                                           fmaxf(acc[i][j][1]+b1, 0.f));
                *(float2*)d1 = make_float2(fmaxf(acc[i][j][2]+b0, 0.f),
                                           fmaxf(acc[i][j][3]+b1, 0.f));
            }
        }
    }
#undef ISSUE_CHUNK
}

// ------------------------------------------------------------------ HMMA GEMM, 64-K chunks, 1 barrier/chunk
// EPI: 1 = fp16 hi/lo split   4 = exp-tile (fused softmax pieces)
// SCA: scale A fragments by per-(row, ktile) Cfac (PV normalization).
#define T64_B  (128*144)

template<int EPI, int COMBOS, int NSTAGE, bool SCA>
__global__ __launch_bounds__(256, 2) void k_gemm64(
    const h16* __restrict__ Ah,
    const h16* __restrict__ Bh, const h16* __restrict__ Bl,
    h16* __restrict__ Ch, h16* __restrict__ Cl,
    const float* __restrict__ bias, const float* __restrict__ Cfac,
    float* __restrict__ Mt, float* __restrict__ St,
    int K, int ldc, size_t sA, size_t sB, size_t sC)
{
    constexpr uint32_t OFF_A = 0;
    constexpr uint32_t OFF_B = T64_B;
    constexpr uint32_t OFF_B2 = 2*T64_B;
    constexpr uint32_t STAGE = (COMBOS >= 2 ? 3 : 2) * T64_B;

    extern __shared__ char smem[];
    uint32_t sb = smem_u32(smem);
    int tid = threadIdx.x;
    int lane = tid & 31, wid = tid >> 5;
    int g = lane >> 2, t = lane & 3;
    int warp_m = (wid & 1) * 64;
    int warp_n = (wid >> 1) * 32;
    int m0 = blockIdx.x * 128, n0 = blockIdx.y * 128, b = blockIdx.z;

    size_t gob = (size_t)(tid >> 3) * K + (tid & 7) * 8;
    uint32_t dob = (uint32_t)((tid >> 3) * 144 + (tid & 7) * 16);

    int lr = ((lane >> 3) & 1) * 8 + (lane & 7);
    int lk = (lane >> 4) * 16;
    uint32_t a_off[4], b_off[2];
#pragma unroll
    for (int i = 0; i < 4; i++) a_off[i] = (uint32_t)((warp_m + i*16 + lr)*144 + lk);
#pragma unroll
    for (int p = 0; p < 2; p++) b_off[p] = (uint32_t)((warp_n + p*16 + lr)*144 + lk);

    const h16* pAh = Ah + (size_t)b*sA + (size_t)m0*K;
    const h16* pBh = Bh + (size_t)b*sB + (size_t)n0*K;
    const h16* pBl = (COMBOS >= 2) ? Bl + (size_t)b*sB + (size_t)n0*K : nullptr;

    float acc[4][4][4];
#pragma unroll
    for (int i = 0; i < 4; i++)
#pragma unroll
        for (int j = 0; j < 4; j++)
#pragma unroll
            for (int r = 0; r < 4; r++) acc[i][j][r] = 0.f;

    __half2 hA[4], hB[4];

#define ISSUE64(sbase, k0) do {                                              \
        _Pragma("unroll")                                                    \
        for (int _i = 0; _i < 4; _i++) {                                     \
            size_t _g = gob + (size_t)(32*_i)*K + (k0);                      \
            uint32_t _d = dob + 32*_i*144;                                   \
            CP16((sbase) + OFF_A + _d, pAh + _g);                            \
            CP16((sbase) + OFF_B + _d, pBh + _g);                            \
            if (COMBOS >= 2) CP16((sbase) + OFF_B2 + _d, pBl + _g);          \
        }                                                                    \
    } while (0)

#define COMPUTE64(basev) do {                                                \
        _Pragma("unroll")                                                    \
        for (int ks = 0; ks < 4; ks++) {                                     \
            uint32_t kb = ks * 32;                                           \
            uint32_t ah[4][4], bh[4][2], bl[4][2];                           \
            _Pragma("unroll")                                                \
            for (int i = 0; i < 4; i++) {                                    \
                LDSM4(ah[i][0], ah[i][1], ah[i][2], ah[i][3],                \
                      (basev) + OFF_A + a_off[i] + kb);                      \
                if (SCA) {                                                   \
                    *(__half2*)&ah[i][0] = __hmul2(*(__half2*)&ah[i][0], hA[i]); \
                    *(__half2*)&ah[i][1] = __hmul2(*(__half2*)&ah[i][1], hB[i]); \
                    *(__half2*)&ah[i][2] = __hmul2(*(__half2*)&ah[i][2], hA[i]); \
                    *(__half2*)&ah[i][3] = __hmul2(*(__half2*)&ah[i][3], hB[i]); \
                }                                                            \
            }                                                                \
            _Pragma("unroll")                                                \
            for (int p = 0; p < 2; p++) {                                    \
                LDSM4(bh[2*p][0], bh[2*p+1][0], bh[2*p][1], bh[2*p+1][1],    \
                      (basev) + OFF_B + b_off[p] + kb);                      \
                if (COMBOS >= 2)                                             \
                    LDSM4(bl[2*p][0], bl[2*p+1][0], bl[2*p][1], bl[2*p+1][1],\
                          (basev) + OFF_B2 + b_off[p] + kb);                 \
            }                                                                \
            _Pragma("unroll")                                                \
            for (int i = 0; i < 4; i++)                                      \
                _Pragma("unroll")                                            \
                for (int j = 0; j < 4; j++) {                                \
                    MMA16816(acc[i][j], ah[i], bh[j]);                       \
                    if (COMBOS >= 2) MMA16816(acc[i][j], ah[i], bl[j]);      \
                }                                                            \
        }                                                                    \
    } while (0)

#define LOAD_CF(ch) do {                                                     \
        if (SCA && ((ch) & 1) == 0) {                                        \
            int kt = (ch) >> 1;                                              \
            _Pragma("unroll")                                                \
            for (int i = 0; i < 4; i++) {                                    \
                float fA = Cfac[((size_t)b*NN + m0 + warp_m + i*16 + g)*16 + kt];     \
                float fB = Cfac[((size_t)b*NN + m0 + warp_m + i*16 + g + 8)*16 + kt]; \
                hA[i] = __half2half2(__float2half_rn(fA));                   \
                hB[i] = __half2half2(__float2half_rn(fB));                   \
            }                                                                \
        }                                                                    \
    } while (0)

    int nchunk = K >> 6;
    if (NSTAGE == 2) {
        ISSUE64(sb, 0);
        CP_COMMIT();
        for (int ch = 0; ch < nchunk; ch++) {
            CP_WAIT(0);
            __syncthreads();
            uint32_t base = sb + (uint32_t)(ch & 1) * STAGE;
            if (ch + 1 < nchunk) {
                ISSUE64(sb + (uint32_t)((ch + 1) & 1) * STAGE, (ch+1) << 6);
                CP_COMMIT();
            }
            LOAD_CF(ch);
            COMPUTE64(base);
        }
    } else {
        ISSUE64(sb, 0);
        CP_COMMIT();
        if (nchunk > 1) ISSUE64(sb + STAGE, 64);
        CP_COMMIT();
        int st = 0;
        for (int ch = 0; ch < nchunk; ch++) {
            CP_WAIT(1);
            __syncthreads();
            uint32_t base = sb + (uint32_t)st * STAGE;
            int st2 = st + 2; if (st2 >= 3) st2 -= 3;
            if (ch + 2 < nchunk) ISSUE64(sb + (uint32_t)st2 * STAGE, (ch+2) << 6);
            CP_COMMIT();
            LOAD_CF(ch);
            COMPUTE64(base);
            st++; if (st == 3) st = 0;
        }
    }

    // ---- epilogue ----
    if (EPI == 4) {
        __syncthreads();
        float* red   = (float*)smem;      // [128][4]
        float* bcast = red + 512;         // [128]
        float* sred  = bcast + 128;       // [128][4]
        int ntile = blockIdx.y;

        float cj0[4], cj1[4];
#pragma unroll
        for (int j = 0; j < 4; j++) {
            int col = n0 + warp_n + j*8 + 2*t;
            cj0[j] = bias[(size_t)b*ldc + col];
            cj1[j] = bias[(size_t)b*ldc + col + 1];
        }

        float mA[4], mB[4];
#pragma unroll
        for (int i = 0; i < 4; i++) {
            mA[i] = -1e30f; mB[i] = -1e30f;
#pragma unroll
            for (int j = 0; j < 4; j++) {
                acc[i][j][0] += cj0[j]; acc[i][j][1] += cj1[j];
                acc[i][j][2] += cj0[j]; acc[i][j][3] += cj1[j];
                mA[i] = fmaxf(mA[i], fmaxf(acc[i][j][0], acc[i][j][1]));
                mB[i] = fmaxf(mB[i], fmaxf(acc[i][j][2], acc[i][j][3]));
            }
            mA[i] = fmaxf(mA[i], __shfl_xor_sync(0xffffffffu, mA[i], 1));
            mA[i] = fmaxf(mA[i], __shfl_xor_sync(0xffffffffu, mA[i], 2));
            mB[i] = fmaxf(mB[i], __shfl_xor_sync(0xffffffffu, mB[i], 1));
            mB[i] = fmaxf(mB[i], __shfl_xor_sync(0xffffffffu, mB[i], 2));
        }
        if (t == 0) {
#pragma unroll
            for (int i = 0; i < 4; i++) {
                red[(warp_m + i*16 + g)*4 + (wid >> 1)]     = mA[i];
                red[(warp_m + i*16 + g + 8)*4 + (wid >> 1)] = mB[i];
            }
        }
        __syncthreads();
        if (tid < 128)
            bcast[tid] = fmaxf(fmaxf(red[tid*4], red[tid*4+1]),
                               fmaxf(red[tid*4+2], red[tid*4+3]));
        __syncthreads();
#pragma unroll
        for (int i = 0; i < 4; i++) {
            int rA = warp_m + i*16 + g, rB = rA + 8;
            float emA = bcast[rA], emB = bcast[rB];
            float sA = 0.f, sB = 0.f;
            size_t oA = (size_t)b*sC + (size_t)(m0 + rA)*ldc + n0;
            size_t oB = oA + 8*(size_t)ldc;
#pragma unroll
            for (int j = 0; j < 4; j++) {
                int cl = warp_n + j*8 + 2*t;
                float p0 = __expf(acc[i][j][0] - emA), p1 = __expf(acc[i][j][1] - emA);
                float p2 = __expf(acc[i][j][2] - emB), p3 = __expf(acc[i][j][3] - emB);
                sA += p0 + p1; sB += p2 + p3;
                *(__half2*)(Ch + oA + cl) = __floats2half2_rn(p0, p1);
                *(__half2*)(Ch + oB + cl) = __floats2half2_rn(p2, p3);
            }
            sA += __shfl_xor_sync(0xffffffffu, sA, 1);
            sA += __shfl_xor_sync(0xffffffffu, sA, 2);
            sB += __shfl_xor_sync(0xffffffffu, sB, 1);
            sB += __shfl_xor_sync(0xffffffffu, sB, 2);
            if (t == 0) {
                sred[rA*4 + (wid >> 1)] = sA;
                sred[rB*4 + (wid >> 1)] = sB;
            }
        }
        __syncthreads();
        if (tid < 128) {
            size_t o = ((size_t)b*NN + m0 + tid)*16 + ntile;
            Mt[o] = bcast[tid];
            St[o] = sred[tid*4] + sred[tid*4+1] + sred[tid*4+2] + sred[tid*4+3];
        }
    } else {
#pragma unroll
        for (int i = 0; i < 4; i++) {
            int row0 = m0 + warp_m + i*16 + g;
#pragma unroll
            for (int j = 0; j < 4; j++) {
                int col = n0 + warp_n + j*8 + 2*t;
                float v0 = acc[i][j][0], v1 = acc[i][j][1];
                float v2 = acc[i][j][2], v3 = acc[i][j][3];
                h16 h0, l0, h1, l1, h2, l2, h3, l3;
                split2(v0, h0, l0); split2(v1, h1, l1);
                split2(v2, h2, l2); split2(v3, h3, l3);
                size_t o0 = (size_t)b*sC + (size_t)row0*ldc + col;
                size_t o1 = o0 + 8*(size_t)ldc;
                *(__half2*)(Ch + o0) = __halves2half2(h0, h1);
                *(__half2*)(Ch + o1) = __halves2half2(h2, h3);
                *(__half2*)(Cl + o0) = __halves2half2(l0, l1);
                *(__half2*)(Cl + o1) = __halves2half2(l2, l3);
            }
        }
    }
#undef ISSUE64
#undef COMPUTE64
#undef LOAD_CF
}

#define S_SMEM   (2*3*T64_B)   // 110592 (2 stages x 3 tiles)
#define PV_SMEM  (3*2*T64_B)   // 110592 (3 stages x 2 tiles)

// ------------------------------------------------------------------ launch
extern "C" void kernel_launch(void* const* d_in, const int* in_sizes, int n_in,
                              void* d_out, int out_size) {
    const float* inp = (const float*)d_in[0];
    const float* Wq  = (const float*)d_in[1];
    const float* bq  = (const float*)d_in[2];
    const float* Wk  = (const float*)d_in[3];
    // bk (d_in[4]) provably drops out of the softmax — unused.
    const float* Wo  = (const float*)d_in[5];
    const float* bo  = (const float*)d_in[6];
    float* out = (float*)d_out;

    float *pCvec, *pMt, *pSt, *pCf;
    h16 *pXh, *pXl, *pXth, *pAph, *pPt, *pAggh, *pAggl;
    h16 *pWth, *pWtl, *pWoth, *pWotl;
    cudaGetSymbolAddress((void**)&pCvec, g_c);
    cudaGetSymbolAddress((void**)&pMt, g_mt);
    cudaGetSymbolAddress((void**)&pSt, g_st);
    cudaGetSymbolAddress((void**)&pCf, g_cf);
    cudaGetSymbolAddress((void**)&pXh, g_Xh);   cudaGetSymbolAddress((void**)&pXl, g_Xl);
    cudaGetSymbolAddress((void**)&pXth, g_Xth);
    cudaGetSymbolAddress((void**)&pAph, g_Aph);
    cudaGetSymbolAddress((void**)&pPt, g_Pt);
    cudaGetSymbolAddress((void**)&pAggh, g_aggh); cudaGetSymbolAddress((void**)&pAggl, g_aggl);
    cudaGetSymbolAddress((void**)&pWth, g_Wth); cudaGetSymbolAddress((void**)&pWtl, g_Wtl);
    cudaGetSymbolAddress((void**)&pWoth, g_Woth); cudaGetSymbolAddress((void**)&pWotl, g_Wotl);

    cudaFuncSetAttribute((const void*)k_gemm<3,3>, cudaFuncAttributeMaxDynamicSharedMemorySize, GEMM_SMEM);
    cudaFuncSetAttribute((const void*)k_gemm<2,3>, cudaFuncAttributeMaxDynamicSharedMemorySize, GEMM_SMEM);
    cudaFuncSetAttribute((const void*)k_gemm64<4,2,2,false>, cudaFuncAttributeMaxDynamicSharedMemorySize, S_SMEM);
    cudaFuncSetAttribute((const void*)k_gemm64<1,1,3,true>,  cudaFuncAttributeMaxDynamicSharedMemorySize, PV_SMEM);

    // 1) W = Wq Wk^T, u = Wk bq
    k_precomp<<<DD + 1, DD>>>(Wq, Wk, bq);
    // 2) tile-based prep: X splits + X^T + c partials + W/Wo splits (one X pass)
    k_prep<<<2560, 256>>>(inp, Wo);
    k_csum<<<ROWS/256, 256>>>();
    // 3) A' = X @ W -> fp16 (hi only; 3 combos)
    k_gemm<3,3><<<dim3(ROWS/128, 2, 1), 256, GEMM_SMEM>>>(
        pXh, pXl, pWth, pWtl, nullptr, pAph, nullptr, DD, DD, 0);
    // 4) S GEMM fused with per-tile softmax: Pt + mt/st   [profiled slot]
    k_gemm64<4,2,2,false><<<dim3(NN/128, NN/128, BB), 256, S_SMEM>>>(
        pAph, pXh, pXl, pPt, nullptr, pCvec, nullptr, pMt, pSt,
        DD, NN, (size_t)NN*DD, (size_t)NN*DD, (size_t)NN*NN);
    // 5) per-row normalization -> Cfac
    k_norm<<<ROWS/256, 256>>>();
    // 6) agg = sum_kt Cfac*Pt @ Xth  (K=2048, 1 combo, 3-stage, A scaled) -> fp16 splits
    k_gemm64<1,1,3,true><<<dim3(NN/128, 2, BB), 256, PV_SMEM>>>(
        pPt, pXth, nullptr, pAggh, pAggl, nullptr, pCf, nullptr, nullptr,
        NN, DD, (size_t)NN*NN, (size_t)DD*NN, (size_t)NN*DD);
    // 7) out = relu(agg @ Wo + bo) -> fp32  (3 combos)
    k_gemm<2,3><<<dim3(ROWS/128, 2, 1), 256, GEMM_SMEM>>>(
        pAggh, pAggl, pWoth, pWotl, out, nullptr, bo, DD, DD, 0);
}

// round 16
// speedup vs baseline: 1.0606x; 1.0606x over previous
#include <cuda_runtime.h>
#include <cuda_fp16.h>
#include <cstdint>

#define DD 256
#define BB 16
#define NN 2048
#define ROWS (BB*NN)

typedef __half h16;

// ------------------------------------------------------------------ scratch
__device__ float g_W[DD*DD];                 // Wq @ Wk^T
__device__ float g_u[DD];                    // Wk @ bq
__device__ float g_c[ROWS];                  // X . u  (per key row)
__device__ float g_cpart[(size_t)ROWS*4];    // c partials per d-tile
__device__ float g_mt[(size_t)ROWS*16];      // per (row, ntile) max
__device__ float g_st[(size_t)ROWS*16];      // per (row, ntile) sum
__device__ float g_cf[(size_t)ROWS*16];      // per (row, ntile) exp(mt-m)/l

__device__ h16 g_Xh[(size_t)ROWS*DD],  g_Xl[(size_t)ROWS*DD];    // X splits (row-major)
__device__ h16 g_Xth[(size_t)BB*DD*NN];                          // X^T (hi only)
__device__ h16 g_Aph[(size_t)ROWS*DD];                           // A' = X@W (fp16)
__device__ h16 g_Pt[(size_t)ROWS*NN];                            // exp(s - m_tile) fp16
__device__ h16 g_aggh[(size_t)ROWS*DD];                          // agg (fp16 hi)
__device__ h16 g_Wth[DD*DD], g_Wtl[DD*DD];   // (WqWk^T)^T splits
__device__ h16 g_Woth[DD*DD], g_Wotl[DD*DD]; // Wo^T splits

// ------------------------------------------------------------------ helpers
__device__ __forceinline__ uint32_t smem_u32(const void* p) {
    uint32_t a;
    asm("{ .reg .u64 t; cvta.to.shared.u64 t, %1; cvt.u32.u64 %0, t; }" : "=r"(a) : "l"(p));
    return a;
}
#define CP16(dst, src) \
    asm volatile("cp.async.cg.shared.global [%0], [%1], 16;" :: "r"(dst), "l"(src))
#define CP_COMMIT() asm volatile("cp.async.commit_group;" ::: "memory")
#define CP_WAIT(n)  asm volatile("cp.async.wait_group %0;" :: "n"(n) : "memory")

#define MMA16816(c, a, b)                                                     \
    asm volatile("mma.sync.aligned.m16n8k16.row.col.f32.f16.f16.f32 "         \
        "{%0,%1,%2,%3},{%4,%5,%6,%7},{%8,%9},{%0,%1,%2,%3};"                  \
        : "+f"((c)[0]), "+f"((c)[1]), "+f"((c)[2]), "+f"((c)[3])              \
        : "r"((a)[0]), "r"((a)[1]), "r"((a)[2]), "r"((a)[3]),                 \
          "r"((b)[0]), "r"((b)[1]))

#define LDSM4(r0, r1, r2, r3, addr)                                           \
    asm volatile("ldmatrix.sync.aligned.m8n8.x4.shared.b16 {%0,%1,%2,%3}, [%4];" \
        : "=r"(r0), "=r"(r1), "=r"(r2), "=r"(r3) : "r"(addr))

__device__ __forceinline__ void split2(float f, h16& h, h16& l) {
    h = __float2half_rn(f);
    l = __float2half_rn(f - __half2float(h));
}
__device__ __forceinline__ uint32_t packh2(h16 a, h16 b) {
    __half2 p = __halves2half2(a, b);
    return *reinterpret_cast<uint32_t*>(&p);
}

// ------------------------------------------------------------------ precompute: W = Wq@Wk^T, u = Wk@bq
__global__ void k_precomp(const float* __restrict__ Wq, const float* __restrict__ Wk,
                          const float* __restrict__ bq) {
    __shared__ float v[DD];
    int bx = blockIdx.x;
    if (bx < DD) {
        v[threadIdx.x] = Wq[bx*DD + threadIdx.x];
        __syncthreads();
        int j = threadIdx.x;
        const float* wk = Wk + j*DD;
        float s = 0.f;
#pragma unroll 8
        for (int e = 0; e < DD; e++) s += v[e] * wk[e];
        g_W[bx*DD + j] = s;
    } else {
        v[threadIdx.x] = bq[threadIdx.x];
        __syncthreads();
        int i = threadIdx.x;
        const float* wk = Wk + i*DD;
        float s = 0.f;
#pragma unroll 8
        for (int e = 0; e < DD; e++) s += wk[e] * v[e];
        g_u[i] = s;
    }
}

// ------------------------------------------------------------------ tile-based prep (one X pass)
__global__ __launch_bounds__(256) void k_prep(const float* __restrict__ X,
                                              const float* __restrict__ Wo) {
    __shared__ float t[64][65];
    __shared__ float us[64];
    int bx = blockIdx.x, tid = threadIdx.x;
    if (bx < 512) {
        int which = bx >> 8, j = bx & 255, d = tid;
        const float* src = which ? Wo : g_W;
        h16* dh = which ? g_Woth : g_Wth;
        h16* dl = which ? g_Wotl : g_Wtl;
        float f = src[d*DD + j];
        split2(f, dh[j*DD + d], dl[j*DD + d]);
        return;
    }
    int idx = bx - 512;
    int n0 = (idx & 31) * 64, d0 = ((idx >> 5) & 3) * 64, b = idx >> 7;
    const float* Xb = X + (size_t)b * NN * DD;

    if (tid < 64) us[tid] = g_u[d0 + tid];
    for (int u = tid; u < 64*16; u += 256) {
        int r = u >> 4, c4 = u & 15;
        float4 v = *(const float4*)(Xb + (size_t)(n0 + r)*DD + d0 + c4*4);
        t[r][c4*4+0] = v.x; t[r][c4*4+1] = v.y; t[r][c4*4+2] = v.z; t[r][c4*4+3] = v.w;
    }
    __syncthreads();

    {
        int r = tid >> 2, part = tid & 3;
        float s = 0.f;
#pragma unroll
        for (int k = 0; k < 16; k++) s += t[r][part*16 + k] * us[part*16 + k];
        s += __shfl_xor_sync(0xffffffffu, s, 1);
        s += __shfl_xor_sync(0xffffffffu, s, 2);
        if (part == 0)
            g_cpart[(size_t)(b*NN + n0 + r)*4 + (d0 >> 6)] = s;
    }

    for (int u = tid; u < 1024; u += 256) {
        int r = u >> 4, cq = u & 15;
        float v0 = t[r][cq*4+0], v1 = t[r][cq*4+1];
        float v2 = t[r][cq*4+2], v3 = t[r][cq*4+3];
        h16 h0,l0,h1,l1,h2,l2,h3,l3;
        split2(v0,h0,l0); split2(v1,h1,l1); split2(v2,h2,l2); split2(v3,h3,l3);
        size_t o = (size_t)(b*NN + n0 + r)*DD + d0 + cq*4;
        *(uint2*)(g_Xh + o) = make_uint2(packh2(h0,h1), packh2(h2,h3));
        *(uint2*)(g_Xl + o) = make_uint2(packh2(l0,l1), packh2(l2,l3));
    }

    size_t ob = (size_t)b * DD * NN;
    for (int u = tid; u < 1024; u += 256) {
        int d = u >> 4, nq = u & 15;
        h16 h0 = __float2half_rn(t[nq*4+0][d]);
        h16 h1 = __float2half_rn(t[nq*4+1][d]);
        h16 h2 = __float2half_rn(t[nq*4+2][d]);
        h16 h3 = __float2half_rn(t[nq*4+3][d]);
        *(uint2*)(g_Xth + ob + (size_t)(d0 + d)*NN + n0 + nq*4) =
            make_uint2(packh2(h0,h1), packh2(h2,h3));
    }
}

__global__ __launch_bounds__(256) void k_csum() {
    int r = blockIdx.x * 256 + threadIdx.x;
    float4 p = *(const float4*)(g_cpart + (size_t)r*4);
    g_c[r] = ((p.x + p.y) + p.z) + p.w;
}

__global__ __launch_bounds__(256) void k_norm() {
    int r = blockIdx.x * 256 + threadIdx.x;
    float mt[16], m = -1e30f;
#pragma unroll
    for (int q = 0; q < 16; q++) {
        mt[q] = g_mt[(size_t)r*16 + q];
        m = fmaxf(m, mt[q]);
    }
    float e[16], l = 0.f;
#pragma unroll
    for (int q = 0; q < 16; q++) {
        e[q] = __expf(mt[q] - m);
        l += g_st[(size_t)r*16 + q] * e[q];
    }
    float inv = 1.f / l;
#pragma unroll
    for (int q = 0; q < 16; q++)
        g_cf[(size_t)r*16 + q] = e[q] * inv;
}

// ------------------------------------------------------------------ HMMA GEMM (32-K chunks, small GEMMs)
#define TPAD   40
#define TILE_B (128*TPAD*2)
#define OFF_AH 0
#define OFF_AL (1*TILE_B)
#define OFF_BH (2*TILE_B)
#define OFF_BL (3*TILE_B)
#define STAGE_B (4*TILE_B)
#define GEMM_SMEM (2*STAGE_B)

// EPI: 2 = bias+relu fp32   3 = fp16 hi-only
template<int EPI, int COMBOS>
__global__ __launch_bounds__(256, 2) void k_gemm(
    const h16* __restrict__ Ah, const h16* __restrict__ Al,
    const h16* __restrict__ Bh, const h16* __restrict__ Bl,
    float* __restrict__ Cf, h16* __restrict__ Ch,
    const float* __restrict__ bias,
    int K, int ldc, size_t sC)
{
    extern __shared__ char smem[];
    uint32_t sb = smem_u32(smem);
    int tid = threadIdx.x;
    int lane = tid & 31, wid = tid >> 5;
    int g = lane >> 2, t = lane & 3;
    int warp_m = (wid & 1) * 64;
    int warp_n = (wid >> 1) * 32;
    int m0 = blockIdx.x * 128, n0 = blockIdx.y * 128;

    size_t go0 = (size_t)(tid >> 2) * K + (tid & 3) * 8;
    size_t go1 = go0 + (size_t)64 * K;
    uint32_t do0 = (uint32_t)((tid >> 2) * 80 + (tid & 3) * 16);
    uint32_t do1 = do0 + 64*80;

    int lr = ((lane >> 3) & 1) * 8 + (lane & 7);
    int lk = (lane >> 4) * 16;
    uint32_t a_off[4], b_off[2];
#pragma unroll
    for (int i = 0; i < 4; i++) a_off[i] = (uint32_t)((warp_m + i*16 + lr)*80 + lk);
#pragma unroll
    for (int p = 0; p < 2; p++) b_off[p] = (uint32_t)((warp_n + p*16 + lr)*80 + lk);

    const h16* pAh = Ah + (size_t)m0*K;
    const h16* pAl = (COMBOS >= 3) ? Al + (size_t)m0*K : nullptr;
    const h16* pBh = Bh + (size_t)n0*K;
    const h16* pBl = (COMBOS >= 2) ? Bl + (size_t)n0*K : nullptr;

    float acc[4][4][4];
#pragma unroll
    for (int i = 0; i < 4; i++)
#pragma unroll
        for (int j = 0; j < 4; j++)
#pragma unroll
            for (int r = 0; r < 4; r++) acc[i][j][r] = 0.f;

#define ISSUE_CHUNK(sbase, k0) do {                                          \
        CP16((sbase) + OFF_AH + do0, pAh + go0 + (k0));                      \
        CP16((sbase) + OFF_AH + do1, pAh + go1 + (k0));                      \
        if (COMBOS >= 3) {                                                   \
            CP16((sbase) + OFF_AL + do0, pAl + go0 + (k0));                  \
            CP16((sbase) + OFF_AL + do1, pAl + go1 + (k0));                  \
        }                                                                    \
        CP16((sbase) + OFF_BH + do0, pBh + go0 + (k0));                      \
        CP16((sbase) + OFF_BH + do1, pBh + go1 + (k0));                      \
        if (COMBOS >= 2) {                                                   \
            CP16((sbase) + OFF_BL + do0, pBl + go0 + (k0));                  \
            CP16((sbase) + OFF_BL + do1, pBl + go1 + (k0));                  \
        }                                                                    \
    } while (0)

    int nchunk = K >> 5;
    ISSUE_CHUNK(sb, 0);
    CP_COMMIT();

    for (int ch = 0; ch < nchunk; ch++) {
        int st = ch & 1;
        if (ch + 1 < nchunk) {
            ISSUE_CHUNK(sb + (uint32_t)(st ^ 1)*STAGE_B, (ch+1) << 5);
            CP_COMMIT();
            CP_WAIT(1);
        } else {
            CP_WAIT(0);
        }
        __syncthreads();

        uint32_t base = sb + (uint32_t)st * STAGE_B;
#pragma unroll
        for (int ks = 0; ks < 2; ks++) {
            uint32_t kb = ks * 32;
            uint32_t ah[4][4], al[4][4], bh[4][2], bl[4][2];
#pragma unroll
            for (int i = 0; i < 4; i++) {
                LDSM4(ah[i][0], ah[i][1], ah[i][2], ah[i][3], base + OFF_AH + a_off[i] + kb);
                if (COMBOS >= 3)
                    LDSM4(al[i][0], al[i][1], al[i][2], al[i][3], base + OFF_AL + a_off[i] + kb);
            }
#pragma unroll
            for (int p = 0; p < 2; p++) {
                LDSM4(bh[2*p][0], bh[2*p+1][0], bh[2*p][1], bh[2*p+1][1],
                      base + OFF_BH + b_off[p] + kb);
                if (COMBOS >= 2)
                    LDSM4(bl[2*p][0], bl[2*p+1][0], bl[2*p][1], bl[2*p+1][1],
                          base + OFF_BL + b_off[p] + kb);
            }
#pragma unroll
            for (int i = 0; i < 4; i++)
#pragma unroll
                for (int j = 0; j < 4; j++) {
                    MMA16816(acc[i][j], ah[i], bh[j]);
                    if (COMBOS >= 2) MMA16816(acc[i][j], ah[i], bl[j]);
                    if (COMBOS >= 3) MMA16816(acc[i][j], al[i], bh[j]);
                }
        }
        __syncthreads();
    }

#pragma unroll
    for (int i = 0; i < 4; i++) {
        int row0 = m0 + warp_m + i*16 + g;
#pragma unroll
        for (int j = 0; j < 4; j++) {
            int col = n0 + warp_n + j*8 + 2*t;
            if (EPI == 3) {
                size_t o0 = (size_t)row0*ldc + col;
                size_t o1 = o0 + 8*(size_t)ldc;
                *(__half2*)(Ch + o0) = __floats2half2_rn(acc[i][j][0], acc[i][j][1]);
                *(__half2*)(Ch + o1) = __floats2half2_rn(acc[i][j][2], acc[i][j][3]);
            } else {
                float b0 = bias[col], b1 = bias[col+1];
                float* d0 = Cf + (size_t)row0*ldc + col;
                float* d1 = d0 + 8*ldc;
                *(float2*)d0 = make_float2(fmaxf(acc[i][j][0]+b0, 0.f),
                                           fmaxf(acc[i][j][1]+b1, 0.f));
                *(float2*)d1 = make_float2(fmaxf(acc[i][j][2]+b0, 0.f),
                                           fmaxf(acc[i][j][3]+b1, 0.f));
            }
        }
    }
#undef ISSUE_CHUNK
}

// ------------------------------------------------------------------ HMMA GEMM, 64-K chunks
// EPI: 4 = exp-tile (fused softmax)   5 = fp16 hi-only
#define T64_B  (128*144)

template<int EPI, int COMBOS, int NSTAGE, bool SCA>
__global__ __launch_bounds__(256, 2) void k_gemm64(
    const h16* __restrict__ Ah,
    const h16* __restrict__ Bh, const h16* __restrict__ Bl,
    h16* __restrict__ Ch,
    const float* __restrict__ bias, const float* __restrict__ Cfac,
    float* __restrict__ Mt, float* __restrict__ St,
    int K, int ldc, size_t sA, size_t sB, size_t sC)
{
    constexpr uint32_t OFF_A = 0;
    constexpr uint32_t OFF_B = T64_B;
    constexpr uint32_t OFF_B2 = 2*T64_B;
    constexpr uint32_t STAGE = (COMBOS >= 2 ? 3 : 2) * T64_B;

    extern __shared__ char smem[];
    uint32_t sb = smem_u32(smem);
    int tid = threadIdx.x;
    int lane = tid & 31, wid = tid >> 5;
    int g = lane >> 2, t = lane & 3;
    int warp_m = (wid & 1) * 64;
    int warp_n = (wid >> 1) * 32;
    int m0 = blockIdx.x * 128, n0 = blockIdx.y * 128, b = blockIdx.z;

    size_t gob = (size_t)(tid >> 3) * K + (tid & 7) * 8;
    uint32_t dob = (uint32_t)((tid >> 3) * 144 + (tid & 7) * 16);

    int lr = ((lane >> 3) & 1) * 8 + (lane & 7);
    int lk = (lane >> 4) * 16;
    uint32_t a_off[4], b_off[2];
#pragma unroll
    for (int i = 0; i < 4; i++) a_off[i] = (uint32_t)((warp_m + i*16 + lr)*144 + lk);
#pragma unroll
    for (int p = 0; p < 2; p++) b_off[p] = (uint32_t)((warp_n + p*16 + lr)*144 + lk);

    const h16* pAh = Ah + (size_t)b*sA + (size_t)m0*K;
    const h16* pBh = Bh + (size_t)b*sB + (size_t)n0*K;
    const h16* pBl = (COMBOS >= 2) ? Bl + (size_t)b*sB + (size_t)n0*K : nullptr;

    float acc[4][4][4];
#pragma unroll
    for (int i = 0; i < 4; i++)
#pragma unroll
        for (int j = 0; j < 4; j++)
#pragma unroll
            for (int r = 0; r < 4; r++) acc[i][j][r] = 0.f;

    __half2 hA[4], hB[4];

#define ISSUE64(sbase, k0) do {                                              \
        _Pragma("unroll")                                                    \
        for (int _i = 0; _i < 4; _i++) {                                     \
            size_t _g = gob + (size_t)(32*_i)*K + (k0);                      \
            uint32_t _d = dob + 32*_i*144;                                   \
            CP16((sbase) + OFF_A + _d, pAh + _g);                            \
            CP16((sbase) + OFF_B + _d, pBh + _g);                            \
            if (COMBOS >= 2) CP16((sbase) + OFF_B2 + _d, pBl + _g);          \
        }                                                                    \
    } while (0)

#define COMPUTE64(basev) do {                                                \
        _Pragma("unroll")                                                    \
        for (int ks = 0; ks < 4; ks++) {                                     \
            uint32_t kb = ks * 32;                                           \
            uint32_t ah[4][4], bh[4][2], bl[4][2];                           \
            _Pragma("unroll")                                                \
            for (int i = 0; i < 4; i++) {                                    \
                LDSM4(ah[i][0], ah[i][1], ah[i][2], ah[i][3],                \
                      (basev) + OFF_A + a_off[i] + kb);                      \
                if (SCA) {                                                   \
                    *(__half2*)&ah[i][0] = __hmul2(*(__half2*)&ah[i][0], hA[i]); \
                    *(__half2*)&ah[i][1] = __hmul2(*(__half2*)&ah[i][1], hB[i]); \
                    *(__half2*)&ah[i][2] = __hmul2(*(__half2*)&ah[i][2], hA[i]); \
                    *(__half2*)&ah[i][3] = __hmul2(*(__half2*)&ah[i][3], hB[i]); \
                }                                                            \
            }                                                                \
            _Pragma("unroll")                                                \
            for (int p = 0; p < 2; p++) {                                    \
                LDSM4(bh[2*p][0], bh[2*p+1][0], bh[2*p][1], bh[2*p+1][1],    \
                      (basev) + OFF_B + b_off[p] + kb);                      \
                if (COMBOS >= 2)                                             \
                    LDSM4(bl[2*p][0], bl[2*p+1][0], bl[2*p][1], bl[2*p+1][1],\
                          (basev) + OFF_B2 + b_off[p] + kb);                 \
            }                                                                \
            _Pragma("unroll")                                                \
            for (int i = 0; i < 4; i++)                                      \
                _Pragma("unroll")                                            \
                for (int j = 0; j < 4; j++) {                                \
                    MMA16816(acc[i][j], ah[i], bh[j]);                       \
                    if (COMBOS >= 2) MMA16816(acc[i][j], ah[i], bl[j]);      \
                }                                                            \
        }                                                                    \
    } while (0)

#define LOAD_CF(ch) do {                                                     \
        if (SCA && ((ch) & 1) == 0) {                                        \
            int kt = (ch) >> 1;                                              \
            _Pragma("unroll")                                                \
            for (int i = 0; i < 4; i++) {                                    \
                float fA = Cfac[((size_t)b*NN + m0 + warp_m + i*16 + g)*16 + kt];     \
                float fB = Cfac[((size_t)b*NN + m0 + warp_m + i*16 + g + 8)*16 + kt]; \
                hA[i] = __half2half2(__float2half_rn(fA));                   \
                hB[i] = __half2half2(__float2half_rn(fB));                   \
            }                                                                \
        }                                                                    \
    } while (0)

    int nchunk = K >> 6;
    if (NSTAGE == 2) {
        ISSUE64(sb, 0);
        CP_COMMIT();
        for (int ch = 0; ch < nchunk; ch++) {
            CP_WAIT(0);
            __syncthreads();
            uint32_t base = sb + (uint32_t)(ch & 1) * STAGE;
            if (ch + 1 < nchunk) {
                ISSUE64(sb + (uint32_t)((ch + 1) & 1) * STAGE, (ch+1) << 6);
                CP_COMMIT();
            }
            LOAD_CF(ch);
            COMPUTE64(base);
        }
    } else {
        ISSUE64(sb, 0);
        CP_COMMIT();
        if (nchunk > 1) ISSUE64(sb + STAGE, 64);
        CP_COMMIT();
        int st = 0;
        for (int ch = 0; ch < nchunk; ch++) {
            CP_WAIT(1);
            __syncthreads();
            uint32_t base = sb + (uint32_t)st * STAGE;
            int st2 = st + 2; if (st2 >= 3) st2 -= 3;
            if (ch + 2 < nchunk) ISSUE64(sb + (uint32_t)st2 * STAGE, (ch+2) << 6);
            CP_COMMIT();
            LOAD_CF(ch);
            COMPUTE64(base);
            st++; if (st == 3) st = 0;
        }
    }

    // ---- epilogue ----
    if (EPI == 4) {
        __syncthreads();
        float* red   = (float*)smem;      // [128][4]
        float* bcast = red + 512;         // [128]
        float* sred  = bcast + 128;       // [128][4]
        int ntile = blockIdx.y;

        float cj0[4], cj1[4];
#pragma unroll
        for (int j = 0; j < 4; j++) {
            int col = n0 + warp_n + j*8 + 2*t;
            cj0[j] = bias[(size_t)b*ldc + col];
            cj1[j] = bias[(size_t)b*ldc + col + 1];
        }

        float mA[4], mB[4];
#pragma unroll
        for (int i = 0; i < 4; i++) {
            mA[i] = -1e30f; mB[i] = -1e30f;
#pragma unroll
            for (int j = 0; j < 4; j++) {
                acc[i][j][0] += cj0[j]; acc[i][j][1] += cj1[j];
                acc[i][j][2] += cj0[j]; acc[i][j][3] += cj1[j];
                mA[i] = fmaxf(mA[i], fmaxf(acc[i][j][0], acc[i][j][1]));
                mB[i] = fmaxf(mB[i], fmaxf(acc[i][j][2], acc[i][j][3]));
            }
            mA[i] = fmaxf(mA[i], __shfl_xor_sync(0xffffffffu, mA[i], 1));
            mA[i] = fmaxf(mA[i], __shfl_xor_sync(0xffffffffu, mA[i], 2));
            mB[i] = fmaxf(mB[i], __shfl_xor_sync(0xffffffffu, mB[i], 1));
            mB[i] = fmaxf(mB[i], __shfl_xor_sync(0xffffffffu, mB[i], 2));
        }
        if (t == 0) {
#pragma unroll
            for (int i = 0; i < 4; i++) {
                red[(warp_m + i*16 + g)*4 + (wid >> 1)]     = mA[i];
                red[(warp_m + i*16 + g + 8)*4 + (wid >> 1)] = mB[i];
            }
        }
        __syncthreads();
        if (tid < 128)
            bcast[tid] = fmaxf(fmaxf(red[tid*4], red[tid*4+1]),
                               fmaxf(red[tid*4+2], red[tid*4+3]));
        __syncthreads();
#pragma unroll
        for (int i = 0; i < 4; i++) {
            int rA = warp_m + i*16 + g, rB = rA + 8;
            float emA = bcast[rA], emB = bcast[rB];
            float sA = 0.f, sB = 0.f;
            size_t oA = (size_t)b*sC + (size_t)(m0 + rA)*ldc + n0;
            size_t oB = oA + 8*(size_t)ldc;
#pragma unroll
            for (int j = 0; j < 4; j++) {
                int cl = warp_n + j*8 + 2*t;
                float p0 = __expf(acc[i][j][0] - emA), p1 = __expf(acc[i][j][1] - emA);
                float p2 = __expf(acc[i][j][2] - emB), p3 = __expf(acc[i][j][3] - emB);
                sA += p0 + p1; sB += p2 + p3;
                *(__half2*)(Ch + oA + cl) = __floats2half2_rn(p0, p1);
                *(__half2*)(Ch + oB + cl) = __floats2half2_rn(p2, p3);
            }
            sA += __shfl_xor_sync(0xffffffffu, sA, 1);
            sA += __shfl_xor_sync(0xffffffffu, sA, 2);
            sB += __shfl_xor_sync(0xffffffffu, sB, 1);
            sB += __shfl_xor_sync(0xffffffffu, sB, 2);
            if (t == 0) {
                sred[rA*4 + (wid >> 1)] = sA;
                sred[rB*4 + (wid >> 1)] = sB;
            }
        }
        __syncthreads();
        if (tid < 128) {
            size_t o = ((size_t)b*NN + m0 + tid)*16 + ntile;
            Mt[o] = bcast[tid];
            St[o] = sred[tid*4] + sred[tid*4+1] + sred[tid*4+2] + sred[tid*4+3];
        }
    } else {
        // EPI 5: fp16 hi-only
#pragma unroll
        for (int i = 0; i < 4; i++) {
            int row0 = m0 + warp_m + i*16 + g;
#pragma unroll
            for (int j = 0; j < 4; j++) {
                int col = n0 + warp_n + j*8 + 2*t;
                size_t o0 = (size_t)b*sC + (size_t)row0*ldc + col;
                size_t o1 = o0 + 8*(size_t)ldc;
                *(__half2*)(Ch + o0) = __floats2half2_rn(acc[i][j][0], acc[i][j][1]);
                *(__half2*)(Ch + o1) = __floats2half2_rn(acc[i][j][2], acc[i][j][3]);
            }
        }
    }
#undef ISSUE64
#undef COMPUTE64
#undef LOAD_CF
}

#define S_SMEM   (2*3*T64_B)   // 110592 (2 stages x 3 tiles)
#define PV_SMEM  (3*2*T64_B)   // 110592 (3 stages x 2 tiles)

// ------------------------------------------------------------------ launch
extern "C" void kernel_launch(void* const* d_in, const int* in_sizes, int n_in,
                              void* d_out, int out_size) {
    const float* inp = (const float*)d_in[0];
    const float* Wq  = (const float*)d_in[1];
    const float* bq  = (const float*)d_in[2];
    const float* Wk  = (const float*)d_in[3];
    // bk (d_in[4]) provably drops out of the softmax — unused.
    const float* Wo  = (const float*)d_in[5];
    const float* bo  = (const float*)d_in[6];
    float* out = (float*)d_out;

    float *pCvec, *pMt, *pSt, *pCf;
    h16 *pXh, *pXl, *pXth, *pAph, *pPt, *pAggh;
    h16 *pWth, *pWtl, *pWoth, *pWotl;
    cudaGetSymbolAddress((void**)&pCvec, g_c);
    cudaGetSymbolAddress((void**)&pMt, g_mt);
    cudaGetSymbolAddress((void**)&pSt, g_st);
    cudaGetSymbolAddress((void**)&pCf, g_cf);
    cudaGetSymbolAddress((void**)&pXh, g_Xh);   cudaGetSymbolAddress((void**)&pXl, g_Xl);
    cudaGetSymbolAddress((void**)&pXth, g_Xth);
    cudaGetSymbolAddress((void**)&pAph, g_Aph);
    cudaGetSymbolAddress((void**)&pPt, g_Pt);
    cudaGetSymbolAddress((void**)&pAggh, g_aggh);
    cudaGetSymbolAddress((void**)&pWth, g_Wth); cudaGetSymbolAddress((void**)&pWtl, g_Wtl);
    cudaGetSymbolAddress((void**)&pWoth, g_Woth); cudaGetSymbolAddress((void**)&pWotl, g_Wotl);

    cudaFuncSetAttribute((const void*)k_gemm<3,2>, cudaFuncAttributeMaxDynamicSharedMemorySize, GEMM_SMEM);
    cudaFuncSetAttribute((const void*)k_gemm<2,2>, cudaFuncAttributeMaxDynamicSharedMemorySize, GEMM_SMEM);
    cudaFuncSetAttribute((const void*)k_gemm64<4,2,2,false>, cudaFuncAttributeMaxDynamicSharedMemorySize, S_SMEM);
    cudaFuncSetAttribute((const void*)k_gemm64<5,1,3,true>,  cudaFuncAttributeMaxDynamicSharedMemorySize, PV_SMEM);

    // 1) W = Wq Wk^T, u = Wk bq
    k_precomp<<<DD + 1, DD>>>(Wq, Wk, bq);
    // 2) tile-based prep: X splits + X^T + c partials + W/Wo splits
    k_prep<<<2560, 256>>>(inp, Wo);
    k_csum<<<ROWS/256, 256>>>();
    // 3) A' = Xh @ W (2 combos: Xh.Wh + Xh.Wl) -> fp16 hi
    k_gemm<3,2><<<dim3(ROWS/128, 2, 1), 256, GEMM_SMEM>>>(
        pXh, nullptr, pWth, pWtl, nullptr, pAph, nullptr, DD, DD, 0);
    // 4) S GEMM fused with per-tile softmax: Pt + mt/st   [profiled slot]
    k_gemm64<4,2,2,false><<<dim3(NN/128, NN/128, BB), 256, S_SMEM>>>(
        pAph, pXh, pXl, pPt, pCvec, nullptr, pMt, pSt,
        DD, NN, (size_t)NN*DD, (size_t)NN*DD, (size_t)NN*NN);
    // 5) per-row normalization -> Cfac
    k_norm<<<ROWS/256, 256>>>();
    // 6) agg = sum_kt Cfac*Pt @ Xth  (K=2048, 1 combo, 3-stage, A scaled) -> fp16 hi
    k_gemm64<5,1,3,true><<<dim3(NN/128, 2, BB), 256, PV_SMEM>>>(
        pPt, pXth, nullptr, pAggh, nullptr, pCf, nullptr, nullptr,
        NN, DD, (size_t)NN*NN, (size_t)DD*NN, (size_t)NN*DD);
    // 7) out = relu(aggh @ Wo + bo)  (2 combos: Ah.Wh + Ah.Wl) -> fp32
    k_gemm<2,2><<<dim3(ROWS/128, 2, 1), 256, GEMM_SMEM>>>(
        pAggh, nullptr, pWoth, pWotl, out, nullptr, bo, DD, DD, 0);
}

// round 17
// speedup vs baseline: 1.0686x; 1.0075x over previous
#include <cuda_runtime.h>
#include <cuda_fp16.h>
#include <cstdint>

#define DD 256
#define BB 16
#define NN 2048
#define ROWS (BB*NN)

typedef __half h16;

// ------------------------------------------------------------------ scratch
__device__ float g_W[DD*DD];                 // Wq @ Wk^T
__device__ float g_u[DD];                    // Wk @ bq
__device__ float g_c[ROWS];                  // X . u  (per key row)
__device__ float g_cpart[(size_t)ROWS*4];    // c partials per d-tile
__device__ float g_mt[(size_t)ROWS*16];      // per (row, ntile) max
__device__ float g_st[(size_t)ROWS*16];      // per (row, ntile) sum
__device__ float g_cf[(size_t)ROWS*16];      // per (row, ntile) exp(mt-m)/l

__device__ h16 g_Xh[(size_t)ROWS*DD],  g_Xl[(size_t)ROWS*DD];    // X splits (row-major)
__device__ h16 g_Xth[(size_t)BB*DD*NN];                          // X^T (hi only)
__device__ h16 g_Aph[(size_t)ROWS*DD];                           // A' = X@W (fp16)
__device__ h16 g_Pt[(size_t)ROWS*NN];                            // exp(s - m_tile) fp16
__device__ h16 g_aggh[(size_t)ROWS*DD];                          // agg (fp16 hi)
__device__ h16 g_Wth[DD*DD], g_Wtl[DD*DD];   // (WqWk^T)^T splits
__device__ h16 g_Woth[DD*DD], g_Wotl[DD*DD]; // Wo^T splits

// ------------------------------------------------------------------ helpers
__device__ __forceinline__ uint32_t smem_u32(const void* p) {
    uint32_t a;
    asm("{ .reg .u64 t; cvta.to.shared.u64 t, %1; cvt.u32.u64 %0, t; }" : "=r"(a) : "l"(p));
    return a;
}
#define CP16(dst, src) \
    asm volatile("cp.async.cg.shared.global [%0], [%1], 16;" :: "r"(dst), "l"(src))
#define CP_COMMIT() asm volatile("cp.async.commit_group;" ::: "memory")
#define CP_WAIT(n)  asm volatile("cp.async.wait_group %0;" :: "n"(n) : "memory")

#define MMA16816(c, a, b)                                                     \
    asm volatile("mma.sync.aligned.m16n8k16.row.col.f32.f16.f16.f32 "         \
        "{%0,%1,%2,%3},{%4,%5,%6,%7},{%8,%9},{%0,%1,%2,%3};"                  \
        : "+f"((c)[0]), "+f"((c)[1]), "+f"((c)[2]), "+f"((c)[3])              \
        : "r"((a)[0]), "r"((a)[1]), "r"((a)[2]), "r"((a)[3]),                 \
          "r"((b)[0]), "r"((b)[1]))

#define LDSM4(r0, r1, r2, r3, addr)                                           \
    asm volatile("ldmatrix.sync.aligned.m8n8.x4.shared.b16 {%0,%1,%2,%3}, [%4];" \
        : "=r"(r0), "=r"(r1), "=r"(r2), "=r"(r3) : "r"(addr))

__device__ __forceinline__ void split2(float f, h16& h, h16& l) {
    h = __float2half_rn(f);
    l = __float2half_rn(f - __half2float(h));
}
__device__ __forceinline__ uint32_t packh2(h16 a, h16 b) {
    __half2 p = __halves2half2(a, b);
    return *reinterpret_cast<uint32_t*>(&p);
}

// ------------------------------------------------------------------ precompute: W = Wq@Wk^T, u = Wk@bq
__global__ void k_precomp(const float* __restrict__ Wq, const float* __restrict__ Wk,
                          const float* __restrict__ bq) {
    __shared__ float v[DD];
    int bx = blockIdx.x;
    if (bx < DD) {
        v[threadIdx.x] = Wq[bx*DD + threadIdx.x];
        __syncthreads();
        int j = threadIdx.x;
        const float* wk = Wk + j*DD;
        float s = 0.f;
#pragma unroll 8
        for (int e = 0; e < DD; e++) s += v[e] * wk[e];
        g_W[bx*DD + j] = s;
    } else {
        v[threadIdx.x] = bq[threadIdx.x];
        __syncthreads();
        int i = threadIdx.x;
        const float* wk = Wk + i*DD;
        float s = 0.f;
#pragma unroll 8
        for (int e = 0; e < DD; e++) s += wk[e] * v[e];
        g_u[i] = s;
    }
}

// ------------------------------------------------------------------ tile-based prep (one X pass)
__global__ __launch_bounds__(256) void k_prep(const float* __restrict__ X,
                                              const float* __restrict__ Wo) {
    __shared__ float t[64][65];
    __shared__ float us[64];
    int bx = blockIdx.x, tid = threadIdx.x;
    if (bx < 512) {
        int which = bx >> 8, j = bx & 255, d = tid;
        const float* src = which ? Wo : g_W;
        h16* dh = which ? g_Woth : g_Wth;
        h16* dl = which ? g_Wotl : g_Wtl;
        float f = src[d*DD + j];
        split2(f, dh[j*DD + d], dl[j*DD + d]);
        return;
    }
    int idx = bx - 512;
    int n0 = (idx & 31) * 64, d0 = ((idx >> 5) & 3) * 64, b = idx >> 7;
    const float* Xb = X + (size_t)b * NN * DD;

    if (tid < 64) us[tid] = g_u[d0 + tid];
    for (int u = tid; u < 64*16; u += 256) {
        int r = u >> 4, c4 = u & 15;
        float4 v = *(const float4*)(Xb + (size_t)(n0 + r)*DD + d0 + c4*4);
        t[r][c4*4+0] = v.x; t[r][c4*4+1] = v.y; t[r][c4*4+2] = v.z; t[r][c4*4+3] = v.w;
    }
    __syncthreads();

    {
        int r = tid >> 2, part = tid & 3;
        float s = 0.f;
#pragma unroll
        for (int k = 0; k < 16; k++) s += t[r][part*16 + k] * us[part*16 + k];
        s += __shfl_xor_sync(0xffffffffu, s, 1);
        s += __shfl_xor_sync(0xffffffffu, s, 2);
        if (part == 0)
            g_cpart[(size_t)(b*NN + n0 + r)*4 + (d0 >> 6)] = s;
    }

    for (int u = tid; u < 1024; u += 256) {
        int r = u >> 4, cq = u & 15;
        float v0 = t[r][cq*4+0], v1 = t[r][cq*4+1];
        float v2 = t[r][cq*4+2], v3 = t[r][cq*4+3];
        h16 h0,l0,h1,l1,h2,l2,h3,l3;
        split2(v0,h0,l0); split2(v1,h1,l1); split2(v2,h2,l2); split2(v3,h3,l3);
        size_t o = (size_t)(b*NN + n0 + r)*DD + d0 + cq*4;
        *(uint2*)(g_Xh + o) = make_uint2(packh2(h0,h1), packh2(h2,h3));
        *(uint2*)(g_Xl + o) = make_uint2(packh2(l0,l1), packh2(l2,l3));
    }

    size_t ob = (size_t)b * DD * NN;
    for (int u = tid; u < 1024; u += 256) {
        int d = u >> 4, nq = u & 15;
        h16 h0 = __float2half_rn(t[nq*4+0][d]);
        h16 h1 = __float2half_rn(t[nq*4+1][d]);
        h16 h2 = __float2half_rn(t[nq*4+2][d]);
        h16 h3 = __float2half_rn(t[nq*4+3][d]);
        *(uint2*)(g_Xth + ob + (size_t)(d0 + d)*NN + n0 + nq*4) =
            make_uint2(packh2(h0,h1), packh2(h2,h3));
    }
}

__global__ __launch_bounds__(256) void k_csum() {
    int r = blockIdx.x * 256 + threadIdx.x;
    float4 p = *(const float4*)(g_cpart + (size_t)r*4);
    g_c[r] = ((p.x + p.y) + p.z) + p.w;
}

__global__ __launch_bounds__(256) void k_norm() {
    int r = blockIdx.x * 256 + threadIdx.x;
    float mt[16], m = -1e30f;
#pragma unroll
    for (int q = 0; q < 16; q++) {
        mt[q] = g_mt[(size_t)r*16 + q];
        m = fmaxf(m, mt[q]);
    }
    float e[16], l = 0.f;
#pragma unroll
    for (int q = 0; q < 16; q++) {
        e[q] = __expf(mt[q] - m);
        l += g_st[(size_t)r*16 + q] * e[q];
    }
    float inv = 1.f / l;
#pragma unroll
    for (int q = 0; q < 16; q++)
        g_cf[(size_t)r*16 + q] = e[q] * inv;
}

// ------------------------------------------------------------------ HMMA GEMM, 64-K chunks, 1 barrier/chunk
// EPI: 4 = exp-tile (fused softmax)   5 = fp16 hi-only   6 = bias+relu fp32
// COMBOS: 2 = A.Bh + A.Bl   1 = A.Bh
// SCA: scale A fragments by per-(row, ktile) Cfac (PV normalization).
#define T64_B  (128*144)

template<int EPI, int COMBOS, int NSTAGE, bool SCA>
__global__ __launch_bounds__(256, 2) void k_gemm64(
    const h16* __restrict__ Ah,
    const h16* __restrict__ Bh, const h16* __restrict__ Bl,
    h16* __restrict__ Ch, float* __restrict__ Cf,
    const float* __restrict__ bias, const float* __restrict__ Cfac,
    float* __restrict__ Mt, float* __restrict__ St,
    int K, int ldc, size_t sA, size_t sB, size_t sC)
{
    constexpr uint32_t OFF_A = 0;
    constexpr uint32_t OFF_B = T64_B;
    constexpr uint32_t OFF_B2 = 2*T64_B;
    constexpr uint32_t STAGE = (COMBOS >= 2 ? 3 : 2) * T64_B;

    extern __shared__ char smem[];
    uint32_t sb = smem_u32(smem);
    int tid = threadIdx.x;
    int lane = tid & 31, wid = tid >> 5;
    int g = lane >> 2, t = lane & 3;
    int warp_m = (wid & 1) * 64;
    int warp_n = (wid >> 1) * 32;
    int m0 = blockIdx.x * 128, n0 = blockIdx.y * 128, b = blockIdx.z;

    size_t gob = (size_t)(tid >> 3) * K + (tid & 7) * 8;
    uint32_t dob = (uint32_t)((tid >> 3) * 144 + (tid & 7) * 16);

    int lr = ((lane >> 3) & 1) * 8 + (lane & 7);
    int lk = (lane >> 4) * 16;
    uint32_t a_off[4], b_off[2];
#pragma unroll
    for (int i = 0; i < 4; i++) a_off[i] = (uint32_t)((warp_m + i*16 + lr)*144 + lk);
#pragma unroll
    for (int p = 0; p < 2; p++) b_off[p] = (uint32_t)((warp_n + p*16 + lr)*144 + lk);

    const h16* pAh = Ah + (size_t)b*sA + (size_t)m0*K;
    const h16* pBh = Bh + (size_t)b*sB + (size_t)n0*K;
    const h16* pBl = (COMBOS >= 2) ? Bl + (size_t)b*sB + (size_t)n0*K : nullptr;

    float acc[4][4][4];
#pragma unroll
    for (int i = 0; i < 4; i++)
#pragma unroll
        for (int j = 0; j < 4; j++)
#pragma unroll
            for (int r = 0; r < 4; r++) acc[i][j][r] = 0.f;

    __half2 hA[4], hB[4];

#define ISSUE64(sbase, k0) do {                                              \
        _Pragma("unroll")                                                    \
        for (int _i = 0; _i < 4; _i++) {                                     \
            size_t _g = gob + (size_t)(32*_i)*K + (k0);                      \
            uint32_t _d = dob + 32*_i*144;                                   \
            CP16((sbase) + OFF_A + _d, pAh + _g);                            \
            CP16((sbase) + OFF_B + _d, pBh + _g);                            \
            if (COMBOS >= 2) CP16((sbase) + OFF_B2 + _d, pBl + _g);          \
        }                                                                    \
    } while (0)

#define COMPUTE64(basev) do {                                                \
        _Pragma("unroll")                                                    \
        for (int ks = 0; ks < 4; ks++) {                                     \
            uint32_t kb = ks * 32;                                           \
            uint32_t ah[4][4], bh[4][2], bl[4][2];                           \
            _Pragma("unroll")                                                \
            for (int i = 0; i < 4; i++) {                                    \
                LDSM4(ah[i][0], ah[i][1], ah[i][2], ah[i][3],                \
                      (basev) + OFF_A + a_off[i] + kb);                      \
                if (SCA) {                                                   \
                    *(__half2*)&ah[i][0] = __hmul2(*(__half2*)&ah[i][0], hA[i]); \
                    *(__half2*)&ah[i][1] = __hmul2(*(__half2*)&ah[i][1], hB[i]); \
                    *(__half2*)&ah[i][2] = __hmul2(*(__half2*)&ah[i][2], hA[i]); \
                    *(__half2*)&ah[i][3] = __hmul2(*(__half2*)&ah[i][3], hB[i]); \
                }                                                            \
            }                                                                \
            _Pragma("unroll")                                                \
            for (int p = 0; p < 2; p++) {                                    \
                LDSM4(bh[2*p][0], bh[2*p+1][0], bh[2*p][1], bh[2*p+1][1],    \
                      (basev) + OFF_B + b_off[p] + kb);                      \
                if (COMBOS >= 2)                                             \
                    LDSM4(bl[2*p][0], bl[2*p+1][0], bl[2*p][1], bl[2*p+1][1],\
                          (basev) + OFF_B2 + b_off[p] + kb);                 \
            }                                                                \
            _Pragma("unroll")                                                \
            for (int i = 0; i < 4; i++)                                      \
                _Pragma("unroll")                                            \
                for (int j = 0; j < 4; j++) {                                \
                    MMA16816(acc[i][j], ah[i], bh[j]);                       \
                    if (COMBOS >= 2) MMA16816(acc[i][j], ah[i], bl[j]);      \
                }                                                            \
        }                                                                    \
    } while (0)

#define LOAD_CF(ch) do {                                                     \
        if (SCA && ((ch) & 1) == 0) {                                        \
            int kt = (ch) >> 1;                                              \
            _Pragma("unroll")                                                \
            for (int i = 0; i < 4; i++) {                                    \
                float fA = Cfac[((size_t)b*NN + m0 + warp_m + i*16 + g)*16 + kt];     \
                float fB = Cfac[((size_t)b*NN + m0 + warp_m + i*16 + g + 8)*16 + kt]; \
                hA[i] = __half2half2(__float2half_rn(fA));                   \
                hB[i] = __half2half2(__float2half_rn(fB));                   \
            }                                                                \
        }                                                                    \
    } while (0)

    int nchunk = K >> 6;
    if (NSTAGE == 2) {
        ISSUE64(sb, 0);
        CP_COMMIT();
        for (int ch = 0; ch < nchunk; ch++) {
            CP_WAIT(0);
            __syncthreads();
            uint32_t base = sb + (uint32_t)(ch & 1) * STAGE;
            if (ch + 1 < nchunk) {
                ISSUE64(sb + (uint32_t)((ch + 1) & 1) * STAGE, (ch+1) << 6);
                CP_COMMIT();
            }
            LOAD_CF(ch);
            COMPUTE64(base);
        }
    } else {
        ISSUE64(sb, 0);
        CP_COMMIT();
        if (nchunk > 1) ISSUE64(sb + STAGE, 64);
        CP_COMMIT();
        int st = 0;
        for (int ch = 0; ch < nchunk; ch++) {
            CP_WAIT(1);
            __syncthreads();
            uint32_t base = sb + (uint32_t)st * STAGE;
            int st2 = st + 2; if (st2 >= 3) st2 -= 3;
            if (ch + 2 < nchunk) ISSUE64(sb + (uint32_t)st2 * STAGE, (ch+2) << 6);
            CP_COMMIT();
            LOAD_CF(ch);
            COMPUTE64(base);
            st++; if (st == 3) st = 0;
        }
    }

    // ---- epilogue ----
    if (EPI == 4) {
        __syncthreads();
        float* red   = (float*)smem;      // [128][4]
        float* bcast = red + 512;         // [128]
        float* sred  = bcast + 128;       // [128][4]
        int ntile = blockIdx.y;

        float cj0[4], cj1[4];
#pragma unroll
        for (int j = 0; j < 4; j++) {
            int col = n0 + warp_n + j*8 + 2*t;
            cj0[j] = bias[(size_t)b*ldc + col];
            cj1[j] = bias[(size_t)b*ldc + col + 1];
        }

        float mA[4], mB[4];
#pragma unroll
        for (int i = 0; i < 4; i++) {
            mA[i] = -1e30f; mB[i] = -1e30f;
#pragma unroll
            for (int j = 0; j < 4; j++) {
                acc[i][j][0] += cj0[j]; acc[i][j][1] += cj1[j];
                acc[i][j][2] += cj0[j]; acc[i][j][3] += cj1[j];
                mA[i] = fmaxf(mA[i], fmaxf(acc[i][j][0], acc[i][j][1]));
                mB[i] = fmaxf(mB[i], fmaxf(acc[i][j][2], acc[i][j][3]));
            }
            mA[i] = fmaxf(mA[i], __shfl_xor_sync(0xffffffffu, mA[i], 1));
            mA[i] = fmaxf(mA[i], __shfl_xor_sync(0xffffffffu, mA[i], 2));
            mB[i] = fmaxf(mB[i], __shfl_xor_sync(0xffffffffu, mB[i], 1));
            mB[i] = fmaxf(mB[i], __shfl_xor_sync(0xffffffffu, mB[i], 2));
        }
        if (t == 0) {
#pragma unroll
            for (int i = 0; i < 4; i++) {
                red[(warp_m + i*16 + g)*4 + (wid >> 1)]     = mA[i];
                red[(warp_m + i*16 + g + 8)*4 + (wid >> 1)] = mB[i];
            }
        }
        __syncthreads();
        if (tid < 128)
            bcast[tid] = fmaxf(fmaxf(red[tid*4], red[tid*4+1]),
                               fmaxf(red[tid*4+2], red[tid*4+3]));
        __syncthreads();
#pragma unroll
        for (int i = 0; i < 4; i++) {
            int rA = warp_m + i*16 + g, rB = rA + 8;
            float emA = bcast[rA], emB = bcast[rB];
            float sA = 0.f, sB = 0.f;
            size_t oA = (size_t)b*sC + (size_t)(m0 + rA)*ldc + n0;
            size_t oB = oA + 8*(size_t)ldc;
#pragma unroll
            for (int j = 0; j < 4; j++) {
                int cl = warp_n + j*8 + 2*t;
                float p0 = __expf(acc[i][j][0] - emA), p1 = __expf(acc[i][j][1] - emA);
                float p2 = __expf(acc[i][j][2] - emB), p3 = __expf(acc[i][j][3] - emB);
                sA += p0 + p1; sB += p2 + p3;
                *(__half2*)(Ch + oA + cl) = __floats2half2_rn(p0, p1);
                *(__half2*)(Ch + oB + cl) = __floats2half2_rn(p2, p3);
            }
            sA += __shfl_xor_sync(0xffffffffu, sA, 1);
            sA += __shfl_xor_sync(0xffffffffu, sA, 2);
            sB += __shfl_xor_sync(0xffffffffu, sB, 1);
            sB += __shfl_xor_sync(0xffffffffu, sB, 2);
            if (t == 0) {
                sred[rA*4 + (wid >> 1)] = sA;
                sred[rB*4 + (wid >> 1)] = sB;
            }
        }
        __syncthreads();
        if (tid < 128) {
            size_t o = ((size_t)b*NN + m0 + tid)*16 + ntile;
            Mt[o] = bcast[tid];
            St[o] = sred[tid*4] + sred[tid*4+1] + sred[tid*4+2] + sred[tid*4+3];
        }
    } else if (EPI == 5) {
        // fp16 hi-only
#pragma unroll
        for (int i = 0; i < 4; i++) {
            int row0 = m0 + warp_m + i*16 + g;
#pragma unroll
            for (int j = 0; j < 4; j++) {
                int col = n0 + warp_n + j*8 + 2*t;
                size_t o0 = (size_t)b*sC + (size_t)row0*ldc + col;
                size_t o1 = o0 + 8*(size_t)ldc;
                *(__half2*)(Ch + o0) = __floats2half2_rn(acc[i][j][0], acc[i][j][1]);
                *(__half2*)(Ch + o1) = __floats2half2_rn(acc[i][j][2], acc[i][j][3]);
            }
        }
    } else {
        // EPI 6: bias + relu fp32
#pragma unroll
        for (int i = 0; i < 4; i++) {
            int row0 = m0 + warp_m + i*16 + g;
#pragma unroll
            for (int j = 0; j < 4; j++) {
                int col = n0 + warp_n + j*8 + 2*t;
                float b0 = bias[col], b1 = bias[col+1];
                float* d0 = Cf + (size_t)row0*ldc + col;
                float* d1 = d0 + 8*ldc;
                *(float2*)d0 = make_float2(fmaxf(acc[i][j][0]+b0, 0.f),
                                           fmaxf(acc[i][j][1]+b1, 0.f));
                *(float2*)d1 = make_float2(fmaxf(acc[i][j][2]+b0, 0.f),
                                           fmaxf(acc[i][j][3]+b1, 0.f));
            }
        }
    }
#undef ISSUE64
#undef COMPUTE64
#undef LOAD_CF
}

#define S_SMEM   (2*3*T64_B)   // 110592 (2 stages x 3 tiles)
#define PV_SMEM  (3*2*T64_B)   // 110592 (3 stages x 2 tiles)

// ------------------------------------------------------------------ launch
extern "C" void kernel_launch(void* const* d_in, const int* in_sizes, int n_in,
                              void* d_out, int out_size) {
    const float* inp = (const float*)d_in[0];
    const float* Wq  = (const float*)d_in[1];
    const float* bq  = (const float*)d_in[2];
    const float* Wk  = (const float*)d_in[3];
    // bk (d_in[4]) provably drops out of the softmax — unused.
    const float* Wo  = (const float*)d_in[5];
    const float* bo  = (const float*)d_in[6];
    float* out = (float*)d_out;

    float *pCvec, *pMt, *pSt, *pCf;
    h16 *pXh, *pXl, *pXth, *pAph, *pPt, *pAggh;
    h16 *pWth, *pWtl, *pWoth, *pWotl;
    cudaGetSymbolAddress((void**)&pCvec, g_c);
    cudaGetSymbolAddress((void**)&pMt, g_mt);
    cudaGetSymbolAddress((void**)&pSt, g_st);
    cudaGetSymbolAddress((void**)&pCf, g_cf);
    cudaGetSymbolAddress((void**)&pXh, g_Xh);   cudaGetSymbolAddress((void**)&pXl, g_Xl);
    cudaGetSymbolAddress((void**)&pXth, g_Xth);
    cudaGetSymbolAddress((void**)&pAph, g_Aph);
    cudaGetSymbolAddress((void**)&pPt, g_Pt);
    cudaGetSymbolAddress((void**)&pAggh, g_aggh);
    cudaGetSymbolAddress((void**)&pWth, g_Wth); cudaGetSymbolAddress((void**)&pWtl, g_Wtl);
    cudaGetSymbolAddress((void**)&pWoth, g_Woth); cudaGetSymbolAddress((void**)&pWotl, g_Wotl);

    cudaFuncSetAttribute((const void*)k_gemm64<4,2,2,false>, cudaFuncAttributeMaxDynamicSharedMemorySize, S_SMEM);
    cudaFuncSetAttribute((const void*)k_gemm64<5,1,3,true>,  cudaFuncAttributeMaxDynamicSharedMemorySize, PV_SMEM);
    cudaFuncSetAttribute((const void*)k_gemm64<5,2,2,false>, cudaFuncAttributeMaxDynamicSharedMemorySize, S_SMEM);
    cudaFuncSetAttribute((const void*)k_gemm64<6,2,2,false>, cudaFuncAttributeMaxDynamicSharedMemorySize, S_SMEM);

    // 1) W = Wq Wk^T, u = Wk bq
    k_precomp<<<DD + 1, DD>>>(Wq, Wk, bq);
    // 2) tile-based prep: X splits + X^T + c partials + W/Wo splits
    k_prep<<<2560, 256>>>(inp, Wo);
    k_csum<<<ROWS/256, 256>>>();
    // 3) A' = Xh @ W (2 combos, 64-K chunks) -> fp16 hi
    k_gemm64<5,2,2,false><<<dim3(ROWS/128, 2, 1), 256, S_SMEM>>>(
        pXh, pWth, pWtl, pAph, nullptr, nullptr, nullptr, nullptr, nullptr,
        DD, DD, 0, 0, 0);
    // 4) S GEMM fused with per-tile softmax: Pt + mt/st   [profiled slot]
    k_gemm64<4,2,2,false><<<dim3(NN/128, NN/128, BB), 256, S_SMEM>>>(
        pAph, pXh, pXl, pPt, nullptr, pCvec, nullptr, pMt, pSt,
        DD, NN, (size_t)NN*DD, (size_t)NN*DD, (size_t)NN*NN);
    // 5) per-row normalization -> Cfac
    k_norm<<<ROWS/256, 256>>>();
    // 6) agg = sum_kt Cfac*Pt @ Xth  (K=2048, 1 combo, 3-stage, A scaled) -> fp16 hi
    k_gemm64<5,1,3,true><<<dim3(NN/128, 2, BB), 256, PV_SMEM>>>(
        pPt, pXth, nullptr, pAggh, nullptr, nullptr, pCf, nullptr, nullptr,
        NN, DD, (size_t)NN*NN, (size_t)DD*NN, (size_t)NN*DD);
    // 7) out = relu(aggh @ Wo + bo)  (2 combos, 64-K chunks) -> fp32
    k_gemm64<6,2,2,false><<<dim3(ROWS/128, 2, 1), 256, S_SMEM>>>(
        pAggh, pWoth, pWotl, nullptr, out, bo, nullptr, nullptr, nullptr,
        DD, DD, 0, 0, 0);
}